// round 16
// baseline (speedup 1.0000x reference)
#include <cuda_runtime.h>
#include <math.h>

#define BB 8192
#define LL 64
#define VV 28
#define PADV 36            // row stride: 144B, 16B-aligned -> LDS.128/STS.128
#define LATENT 32
#define PAD_TOKEN 26
#define EOS_TOKEN 27
#define EPSF 1e-7f
#define NSLOTS 128
#define RPB 4              // rows per block = warps per block
#define TPB 128
#define NGRID (BB / RPB)   // 2048

// Cross-block accumulators. Statically zero; finalize re-zeroes after use so
// every kernel_launch (graph replay) starts from zero (deterministic).
__device__ float g_letter[VV][NSLOTS];
__device__ float g_scal[NSLOTS][8];

__constant__ float c_freq[VV] = {
    0.0817f, 0.0149f, 0.0278f, 0.0425f, 0.127f,  0.0223f, 0.0202f,
    0.0609f, 0.0697f, 0.0015f, 0.0077f, 0.0403f, 0.0241f, 0.0675f,
    0.0751f, 0.0193f, 0.001f,  0.0599f, 0.0633f, 0.0906f, 0.0276f,
    0.0098f, 0.0236f, 0.0015f, 0.0197f, 0.0007f, 0.0f,    0.0f};

__device__ __forceinline__ float wredf(float v) {
#pragma unroll
    for (int o = 16; o > 0; o >>= 1)
        v += __shfl_down_sync(0xffffffffu, v, o);
    return v;
}

// Window-product accumulation for one start index; early exit on exact 0
// (mask or underflow) is exact since all remaining terms are then 0.
__device__ __forceinline__ float consec_run(const float* __restrict__ aj,
                                            const float* __restrict__ swp,
                                            int pos) {
    float p = aj[pos];
    float acc = p;                 // m=1, weight 1
    const int rem = 62 - pos;
    int k = 1;
    while (k + 3 <= rem) {
        if (p == 0.f) break;
        float a0 = aj[pos + k], a1 = aj[pos + k + 1];
        float a2 = aj[pos + k + 2], a3 = aj[pos + k + 3];
        p *= a0; acc += swp[k + 1] * p;
        p *= a1; acc += swp[k + 2] * p;
        p *= a2; acc += swp[k + 3] * p;
        p *= a3; acc += swp[k + 4] * p;
        k += 4;
    }
    while (k <= rem && p != 0.f) {
        p *= aj[pos + k];
        acc += swp[k + 1] * p;
        k++;
    }
    return acc;
}

// Warp-per-row: warp w owns batch row b0+w end to end. All pipeline syncs are
// __syncwarp; exactly ONE __syncthreads before the cross-warp reduce.
__global__ void __launch_bounds__(TPB) vae_main(
    const float* __restrict__ x,
    const float* __restrict__ rec,
    const float* __restrict__ zm,
    const float* __restrict__ zlv,
    const float* __restrict__ cls) {
    __shared__ float sr[RPB][LL * PADV];   // staging: x first, then rec
    __shared__ float sadj[RPB][LL];        // adjacent dots (63 used)
    __shared__ int   stgt[RPB][LL];
    __shared__ float smexp[RPB][LL];
    __shared__ float swpow[LL];            // m^2.5 = m*m*sqrt(m)
    __shared__ float spart[RPB][VV];       // per-warp letter sums
    __shared__ float sred[6][RPB];

    const int tid  = threadIdx.x;
    const int warp = tid >> 5;             // = row within block
    const int lane = tid & 31;
    const int b0   = blockIdx.x * RPB;
    const int slot = blockIdx.x & (NSLOTS - 1);

    // --- independent early loads: KL (all 128 threads = 4 rows x 32) ---
    const float zmv  = zm[(size_t)b0 * LATENT + tid];
    const float zlvv = zlv[(size_t)b0 * LATENT + tid];
    const float clsv = (lane == 0) ? cls[b0 + warp] : 0.f;

    // swpow: every warp writes the full table with identical values (benign
    // race); each warp's own writes are ordered by its __syncwarp below.
    {
        float f1 = (float)lane;
        swpow[lane] = f1 * f1 * sqrtf(f1);
        float f2 = (float)(lane + 32);
        swpow[lane + 32] = f2 * f2 * sqrtf(f2);
    }

    // ---- Phase A: warp stages ITS row of x (14 coalesced LDG.128) ----
    {
        const float4* gx = (const float4*)(x + (size_t)(b0 + warp) * (LL * VV));
#pragma unroll
        for (int j = 0; j < 14; j++) {
            int i = lane + j * 32;
            float4 v = gx[i];
            int p = i / 7, c = i - p * 7;
            *(float4*)&sr[warp][p * PADV + c * 4] = v;
        }
    }
    __syncwarp();

    // --- argmax for this lane's 2 positions (LDS.128, conflict-free) ---
    int am1 = 0, am2 = 0;
    {
        const float4* xr = (const float4*)&sr[warp][lane * PADV];
        float bv = -INFINITY;
#pragma unroll
        for (int c = 0; c < 7; c++) {
            float4 v = xr[c];
            if (v.x > bv) { bv = v.x; am1 = c * 4 + 0; }
            if (v.y > bv) { bv = v.y; am1 = c * 4 + 1; }
            if (v.z > bv) { bv = v.z; am1 = c * 4 + 2; }
            if (v.w > bv) { bv = v.w; am1 = c * 4 + 3; }
        }
        const float4* xr2 = (const float4*)&sr[warp][(lane + 32) * PADV];
        bv = -INFINITY;
#pragma unroll
        for (int c = 0; c < 7; c++) {
            float4 v = xr2[c];
            if (v.x > bv) { bv = v.x; am2 = c * 4 + 0; }
            if (v.y > bv) { bv = v.y; am2 = c * 4 + 1; }
            if (v.z > bv) { bv = v.z; am2 = c * 4 + 2; }
            if (v.w > bv) { bv = v.w; am2 = c * 4 + 3; }
        }
    }
    stgt[warp][lane]      = am1;
    stgt[warp][lane + 32] = am2;
    const float m1  = (am1 != PAD_TOKEN) ? 1.f : 0.f;
    const float me1 = (am1 != PAD_TOKEN && am1 != EOS_TOKEN) ? 1.f : 0.f;
    const float m2  = (am2 != PAD_TOKEN) ? 1.f : 0.f;
    const float me2 = (am2 != PAD_TOKEN && am2 != EOS_TOKEN) ? 1.f : 0.f;
    smexp[warp][lane]      = me1;
    smexp[warp][lane + 32] = me2;
    __syncwarp();   // all argmax reads done before this warp's row overwrite

    // ---- Phase B: warp stages ITS row of rec into the SAME buffer ----
    {
        const float4* gr = (const float4*)(rec + (size_t)(b0 + warp) * (LL * VV));
#pragma unroll
        for (int j = 0; j < 14; j++) {
            int i = lane + j * 32;
            float4 v = gr[i];
            int p = i / 7, c = i - p * 7;
            *(float4*)&sr[warp][p * PADV + c * 4] = v;
        }
    }
    __syncwarp();

    // --- reconstruction CE for both positions ---
    float pt1 = sr[warp][lane * PADV + am1];
    float pt2 = sr[warp][(lane + 32) * PADV + am2];
    pt1 = fminf(fmaxf(pt1, EPSF), 1.f);
    pt2 = fminf(fmaxf(pt2, EPSF), 1.f);
    float v_rec = -(m1 * __logf(pt1) + m2 * __logf(pt2));

    // --- adjacent dots: j1 = lane, j2 = lane+32 (lane 31 skips j2=63) ---
    {
        const float4* a4 = (const float4*)&sr[warp][lane * PADV];
        const float4* c4 = (const float4*)&sr[warp][(lane + 1) * PADV];
        float d0 = 0.f, d1 = 0.f, d2 = 0.f, d3 = 0.f;
#pragma unroll
        for (int c = 0; c < 7; c++) {
            float4 a = a4[c];
            float4 b = c4[c];
            d0 += a.x * b.x; d1 += a.y * b.y;
            d2 += a.z * b.z; d3 += a.w * b.w;
        }
        float mm = (stgt[warp][lane + 1] != PAD_TOKEN) ? 1.f : 0.f;
        sadj[warp][lane] = ((d0 + d1) + (d2 + d3)) * mm;
    }
    if (lane < 31) {
        const float4* a4 = (const float4*)&sr[warp][(lane + 32) * PADV];
        const float4* c4 = (const float4*)&sr[warp][(lane + 33) * PADV];
        float d0 = 0.f, d1 = 0.f, d2 = 0.f, d3 = 0.f;
#pragma unroll
        for (int c = 0; c < 7; c++) {
            float4 a = a4[c];
            float4 b = c4[c];
            d0 += a.x * b.x; d1 += a.y * b.y;
            d2 += a.z * b.z; d3 += a.w * b.w;
        }
        float mm = (stgt[warp][lane + 33] != PAD_TOKEN) ? 1.f : 0.f;
        sadj[warp][lane + 32] = ((d0 + d1) + (d2 + d3)) * mm;
    }
    __syncwarp();

    // --- consecutive similarity: lane covers starts {lane, 62-lane} ---
    float v_consec = consec_run(sadj[warp], swpow, lane);
    if (lane != 31)
        v_consec += consec_run(sadj[warp], swpow, 62 - lane);

    // --- per-letter masked sums: lanes 0..27, 64 terms, 2 ILP chains.
    // Across lanes addresses are consecutive words -> conflict-free.
    if (lane < VV) {
        const float* base = &sr[warp][lane];
        const float* mex  = smexp[warp];
        float ls0 = 0.f, ls1 = 0.f;
#pragma unroll
        for (int l = 0; l < LL; l += 2) {
            ls0 += base[l * PADV] * mex[l];
            ls1 += base[(l + 1) * PADV] * mex[l + 1];
        }
        spart[warp][lane] = ls0 + ls1;
    }

    // --- KL + classifier terms ---
    float v_kl  = 1.f + zlvv - zmv * zmv - __expf(zlvv);
    float v_cls = (lane == 0) ? __logf(clsv + EPSF) : 0.f;

    // --- per-warp reductions (warp-uniform shuffles) ---
    float r0 = wredf(v_rec);
    float r1 = wredf(m1 + m2);
    float r2 = wredf(me1 + me2);
    float r3 = wredf(v_consec);
    float r4 = wredf(v_kl);
    float r5 = wredf(v_cls);
    if (lane == 0) {
        sred[0][warp] = r0; sred[1][warp] = r1; sred[2][warp] = r2;
        sred[3][warp] = r3; sred[4][warp] = r4; sred[5][warp] = r5;
    }

    // ---- the ONE block barrier: cross-warp combine + global atomics ----
    __syncthreads();

    if (tid < 6) {
        const float* sq = sred[tid];
        float s = (sq[0] + sq[1]) + (sq[2] + sq[3]);
        atomicAdd(&g_scal[slot][tid], s);
    }
    if (warp == 1 && lane < VV) {
        float t = (spart[0][lane] + spart[1][lane]) +
                  (spart[2][lane] + spart[3][lane]);
        atomicAdd(&g_letter[lane][slot], t);
    }

    // PDL: all this CTA's global atomics are issued above (program order);
    // allow the dependent finalize grid to begin launching.
    asm volatile("griddepcontrol.launch_dependents;" ::: "memory");
}

__global__ void __launch_bounds__(256) vae_finalize(float* __restrict__ out) {
    __shared__ float s_sl[VV];
    __shared__ float s_sc[4][6];
    const int tid  = threadIdx.x;
    const int warp = tid >> 5;
    const int lane = tid & 31;

    // PDL: block until the primary grid's memory ops are visible.
    asm volatile("griddepcontrol.wait;" ::: "memory");

    // letters: 8 threads per letter, each reads 16 contiguous slots (4x float4)
    if (tid < VV * 8) {
        const int letter = tid >> 3;
        const int sub    = tid & 7;
        const float4* p = (const float4*)&g_letter[letter][sub * 16];
        float4 a = __ldcg(p);
        float4 b = __ldcg(p + 1);
        float4 c = __ldcg(p + 2);
        float4 d = __ldcg(p + 3);
        float s = (((a.x + a.y) + (a.z + a.w)) + ((b.x + b.y) + (b.z + b.w))) +
                  (((c.x + c.y) + (c.z + c.w)) + ((d.x + d.y) + (d.z + d.w)));
        s += __shfl_down_sync(0xffffffffu, s, 4, 8);
        s += __shfl_down_sync(0xffffffffu, s, 2, 8);
        s += __shfl_down_sync(0xffffffffu, s, 1, 8);
        if (sub == 0) s_sl[letter] = s;
    }

    // scalars: thread t (<128) owns slot t's contiguous 32B row
    float sc[6] = {0.f, 0.f, 0.f, 0.f, 0.f, 0.f};
    if (tid < NSLOTS) {
        const float4* rowp = (const float4*)g_scal[tid];
        float4 a = __ldcg(rowp);
        float4 b = __ldcg(rowp + 1);
        sc[0] = a.x; sc[1] = a.y; sc[2] = a.z;
        sc[3] = a.w; sc[4] = b.x; sc[5] = b.y;
    }
    if (warp < 4) {
#pragma unroll
        for (int q = 0; q < 6; q++) {
#pragma unroll
            for (int o = 16; o > 0; o >>= 1)
                sc[q] += __shfl_down_sync(0xffffffffu, sc[q], o);
            if (lane == 0) s_sc[warp][q] = sc[q];
        }
    }
    __syncthreads();

    // re-zero accumulators early (independent stores overlap the tail below)
    {
        float* pl = &g_letter[0][0];
        for (int j = tid; j < VV * NSLOTS; j += 256) pl[j] = 0.f;
        float* ps = &g_scal[0][0];
        for (int j = tid; j < NSLOTS * 8; j += 256) ps[j] = 0.f;
    }

    // all-float tail: warp 0 computes frequency penalty in parallel
    if (warp == 0) {
        float ss[6];
#pragma unroll
        for (int q = 0; q < 6; q++)
            ss[q] = (s_sc[0][q] + s_sc[1][q]) + (s_sc[2][q] + s_sc[3][q]);

        float inv_me = 1.0f / ss[2];
        float d = 0.f;
        if (lane < VV) {
            d = s_sl[lane] * inv_me - c_freq[lane];
            d = fmaxf(d, 0.f);
        }
        float fp = wredf(d);

        if (lane == 0) {
            float rec_loss = ss[0] / ss[1];
            float kl_loss  = -0.5f * ss[4] * (1.0f / (float)(BB * LATENT));
            float cls_loss = -ss[5] * (1.0f / (float)BB);
            out[0] = rec_loss + 0.1f * kl_loss + 2.0f * cls_loss +
                     0.2f * ss[3] + 0.5f * fp;
        }
    }
}

extern "C" void kernel_launch(void* const* d_in, const int* in_sizes, int n_in,
                              void* d_out, int out_size) {
    (void)in_sizes; (void)n_in; (void)out_size;
    const float* x   = (const float*)d_in[0];
    const float* rec = (const float*)d_in[1];
    const float* zm  = (const float*)d_in[2];
    const float* zlv = (const float*)d_in[3];
    const float* cls = (const float*)d_in[4];

    vae_main<<<NGRID, TPB>>>(x, rec, zm, zlv, cls);

    // Finalize via PDL so its launch latency overlaps vae_main's execution.
    cudaLaunchConfig_t cfg = {};
    cfg.gridDim  = dim3(1, 1, 1);
    cfg.blockDim = dim3(256, 1, 1);
    cfg.dynamicSmemBytes = 0;
    cfg.stream = 0;
    cudaLaunchAttribute attrs[1];
    attrs[0].id = cudaLaunchAttributeProgrammaticStreamSerialization;
    attrs[0].val.programmaticStreamSerializationAllowed = 1;
    cfg.attrs = attrs;
    cfg.numAttrs = 1;
    float* outp = (float*)d_out;
    cudaLaunchKernelEx(&cfg, vae_finalize, outp);
}

// round 17
// speedup vs baseline: 1.1159x; 1.1159x over previous
#include <cuda_runtime.h>
#include <math.h>

#define BB 8192
#define LL 64
#define VV 28
#define PADV 36            // row stride: 144B, 16B-aligned -> LDS.128/STS.128;
                           // phase-of-8 lanes cover all 32 banks -> conflict-free
#define LATENT 32
#define PAD_TOKEN 26
#define EOS_TOKEN 27
#define EPSF 1e-7f
#define NSLOTS 64
#define RPB 2              // rows per block
#define TPB 128
#define NGRID (BB / RPB)   // 4096

// Cross-block accumulators. Statically zero; finalize re-zeroes after use so
// every kernel_launch (graph replay) starts from zero (deterministic).
// g_letter is letter-major so finalize reads are contiguous per letter.
__device__ float g_letter[VV][NSLOTS];
__device__ float g_scal[NSLOTS][8];

__constant__ float c_freq[VV] = {
    0.0817f, 0.0149f, 0.0278f, 0.0425f, 0.127f,  0.0223f, 0.0202f,
    0.0609f, 0.0697f, 0.0015f, 0.0077f, 0.0403f, 0.0241f, 0.0675f,
    0.0751f, 0.0193f, 0.001f,  0.0599f, 0.0633f, 0.0906f, 0.0276f,
    0.0098f, 0.0236f, 0.0015f, 0.0197f, 0.0007f, 0.0f,    0.0f};

__device__ __forceinline__ float wredf(float v) {
#pragma unroll
    for (int o = 16; o > 0; o >>= 1)
        v += __shfl_down_sync(0xffffffffu, v, o);
    return v;
}

__global__ void __launch_bounds__(TPB) vae_main(
    const float* __restrict__ x,
    const float* __restrict__ rec,
    const float* __restrict__ zm,
    const float* __restrict__ zlv,
    const float* __restrict__ cls) {
    // Single staging buffer, used for x first (argmax), then rec.
    __shared__ float sr[RPB][LL * PADV];
    __shared__ float sadj[RPB][LL];        // adjacent dots (63 used)
    __shared__ int   stgt[RPB][LL];
    __shared__ float smexp[RPB][LL];
    __shared__ float swpow[LL];            // m^2.5 = m*m*sqrt(m)
    __shared__ float spart[RPB][VV];       // letter partial (upper half)
    __shared__ float sred[6][TPB / 32];

    const int tid  = threadIdx.x;
    const int b0   = blockIdx.x * RPB;
    const int slot = blockIdx.x & (NSLOTS - 1);
    const int row  = tid >> 6;             // 0..1
    const int pos  = tid & 63;
    const int warp = tid >> 5;
    const int lane = tid & 31;

    // --- early independent global loads (KL / classifier) ---
    float zmv = 0.f, zlvv = 0.f;
    if (tid < RPB * LATENT) {
        zmv  = zm[(size_t)b0 * LATENT + tid];
        zlvv = zlv[(size_t)b0 * LATENT + tid];
    }
    float clsv = 0.f;
    if (tid >= 64 && tid < 64 + RPB) clsv = cls[b0 + (tid - 64)];

    // ---- Phase A: stage x coalesced into padded smem (STS.128) ----
    {
        const float4* gx = (const float4*)(x + (size_t)b0 * (LL * VV));
#pragma unroll
        for (int j = 0; j < (RPB * LL * VV / 4) / TPB; j++) {   // 7 iters
            int i = tid + j * TPB;
            float4 v = gx[i];
            int r   = i / (LL * VV / 4);
            int rem = i - r * (LL * VV / 4);
            int p   = rem / 7;
            int c   = rem - p * 7;
            *(float4*)&sr[r][p * PADV + c * 4] = v;   // 16B-aligned
        }
    }
    if (tid < LL) {
        float ft = (float)tid;
        swpow[tid] = ft * ft * sqrtf(ft);   // tid^2.5, no powf
    }
    __syncthreads();

    // --- argmax from smem via LDS.128 (conflict-free row reads) ---
    int am = 0;
    {
        const float4* xr = (const float4*)&sr[row][pos * PADV];
        float bv = -INFINITY;
#pragma unroll
        for (int c = 0; c < 7; c++) {
            float4 v = xr[c];
            if (v.x > bv) { bv = v.x; am = c * 4 + 0; }
            if (v.y > bv) { bv = v.y; am = c * 4 + 1; }
            if (v.z > bv) { bv = v.z; am = c * 4 + 2; }
            if (v.w > bv) { bv = v.w; am = c * 4 + 3; }
        }
    }
    stgt[row][pos] = am;
    const float m  = (am != PAD_TOKEN) ? 1.f : 0.f;
    const float me = (am != PAD_TOKEN && am != EOS_TOKEN) ? 1.f : 0.f;
    smexp[row][pos] = me;
    __syncthreads();   // all argmax reads done before buffer overwrite

    // ---- Phase B: stage rec coalesced into the SAME buffer (STS.128) ----
    {
        const float4* gr = (const float4*)(rec + (size_t)b0 * (LL * VV));
#pragma unroll
        for (int j = 0; j < (RPB * LL * VV / 4) / TPB; j++) {   // 7 iters
            int i = tid + j * TPB;
            float4 v = gr[i];
            int r   = i / (LL * VV / 4);
            int rem = i - r * (LL * VV / 4);
            int p   = rem / 7;
            int c   = rem - p * 7;
            *(float4*)&sr[r][p * PADV + c * 4] = v;
        }
    }
    __syncthreads();

    // --- reconstruction CE (clip + log on target prob) ---
    float pt = sr[row][pos * PADV + am];
    pt = fminf(fmaxf(pt, EPSF), 1.f);
    float v_rec = -m * __logf(pt);

    // --- adjacent[j] = dot(rec[j], rec[j+1]) * (tgt[j+1] != PAD), LDS.128 ---
    float adjv = 0.f;
    if (pos < LL - 1) {
        const float4* a4 = (const float4*)&sr[row][pos * PADV];
        const float4* c4 = (const float4*)&sr[row][(pos + 1) * PADV];
        float d0 = 0.f, d1 = 0.f, d2 = 0.f, d3 = 0.f;
#pragma unroll
        for (int c = 0; c < 7; c++) {
            float4 a = a4[c];
            float4 b = c4[c];
            d0 += a.x * b.x;
            d1 += a.y * b.y;
            d2 += a.z * b.z;
            d3 += a.w * b.w;
        }
        float mm = (stgt[row][pos + 1] != PAD_TOKEN) ? 1.f : 0.f;
        adjv = ((d0 + d1) + (d2 + d3)) * mm;
    }
    sadj[row][pos] = adjv;
    __syncthreads();

    // --- consecutive similarity: running window product, early exit on 0 ---
    // window products hit exact 0 fast (mask or underflow); remaining terms
    // are then exactly 0, so the break is exact.
    float v_consec = 0.f;
    if (pos < LL - 1) {
        const float* aj = sadj[row];
        float p = aj[pos];
        v_consec = p;                 // m=1, weight 1
        const int rem = 62 - pos;     // k ranges 1..rem
        int k = 1;
        while (k + 3 <= rem) {
            if (p == 0.f) break;
            float a0 = aj[pos + k], a1 = aj[pos + k + 1];
            float a2 = aj[pos + k + 2], a3 = aj[pos + k + 3];
            p *= a0; v_consec += swpow[k + 1] * p;
            p *= a1; v_consec += swpow[k + 2] * p;
            p *= a2; v_consec += swpow[k + 3] * p;
            p *= a3; v_consec += swpow[k + 4] * p;
            k += 4;
        }
        while (k <= rem && p != 0.f) {
            p *= aj[pos + k];
            v_consec += swpow[k + 1] * p;
            k++;
        }
    }

    // --- per-letter masked sums: 56 threads/row, 32 FMAs (2 ILP chains).
    // Across lanes the addresses are consecutive words -> conflict-free.
    const int half   = (pos >= 32) ? 1 : 0;
    const int letter = pos - half * 32;
    float ls = 0.f;
    if (letter < VV) {
        const float* base = &sr[row][half * 32 * PADV + letter];
        const float* mex  = &smexp[row][half * 32];
        float ls0 = 0.f, ls1 = 0.f;
#pragma unroll
        for (int l = 0; l < 32; l += 2) {
            ls0 += base[l * PADV] * mex[l];
            ls1 += base[(l + 1) * PADV] * mex[l + 1];
        }
        ls = ls0 + ls1;
        if (half) spart[row][letter] = ls;
    }

    // --- KL + classifier terms ---
    float v_kl  = (tid < RPB * LATENT) ? (1.f + zlvv - zmv * zmv - __expf(zlvv)) : 0.f;
    float v_cls = (tid >= 64 && tid < 64 + RPB) ? __logf(clsv + EPSF) : 0.f;

    // --- block reduction (float) ---
    float r0 = wredf(v_rec);
    float r1 = wredf(m);
    float r2 = wredf(me);
    float r3 = wredf(v_consec);
    float r4 = wredf(v_kl);
    float r5 = wredf(v_cls);
    if (lane == 0) {
        sred[0][warp] = r0; sred[1][warp] = r1; sred[2][warp] = r2;
        sred[3][warp] = r3; sred[4][warp] = r4; sred[5][warp] = r5;
    }
    __syncthreads();

    if (!half && letter < VV)
        atomicAdd(&g_letter[letter][slot], ls + spart[row][letter]);

    if (tid < 6) {
        const float* sq = sred[tid];
        float s = (sq[0] + sq[1]) + (sq[2] + sq[3]);
        atomicAdd(&g_scal[slot][tid], s);
    }

    // PDL: all this CTA's global atomics are issued above (program order);
    // allow the dependent finalize grid to begin launching.
    asm volatile("griddepcontrol.launch_dependents;" ::: "memory");
}

__global__ void __launch_bounds__(256) vae_finalize(float* __restrict__ out) {
    __shared__ float s_sl[VV];
    __shared__ float s_sc[2][6];
    const int tid  = threadIdx.x;
    const int warp = tid >> 5;
    const int lane = tid & 31;

    // PDL: block until the primary grid's memory ops are visible.
    asm volatile("griddepcontrol.wait;" ::: "memory");

    // letters: 8 threads per letter, each reads 8 contiguous slots (2x float4)
    if (tid < VV * 8) {
        const int letter = tid >> 3;
        const int sub    = tid & 7;
        const float4* p = (const float4*)&g_letter[letter][sub * 8];
        float4 a = __ldcg(p);
        float4 b = __ldcg(p + 1);
        float s = ((a.x + a.y) + (a.z + a.w)) + ((b.x + b.y) + (b.z + b.w));
        s += __shfl_down_sync(0xffffffffu, s, 4, 8);
        s += __shfl_down_sync(0xffffffffu, s, 2, 8);
        s += __shfl_down_sync(0xffffffffu, s, 1, 8);
        if (sub == 0) s_sl[letter] = s;
    }

    // scalars: thread t (<64) owns slot t's contiguous 32B row
    float sc[6] = {0.f, 0.f, 0.f, 0.f, 0.f, 0.f};
    if (tid < NSLOTS) {
        const float4* rowp = (const float4*)g_scal[tid];
        float4 a = __ldcg(rowp);
        float4 b = __ldcg(rowp + 1);
        sc[0] = a.x; sc[1] = a.y; sc[2] = a.z;
        sc[3] = a.w; sc[4] = b.x; sc[5] = b.y;
    }
    if (warp < 2) {
#pragma unroll
        for (int q = 0; q < 6; q++) {
#pragma unroll
            for (int o = 16; o > 0; o >>= 1)
                sc[q] += __shfl_down_sync(0xffffffffu, sc[q], o);
            if (lane == 0) s_sc[warp][q] = sc[q];
        }
    }
    __syncthreads();

    // re-zero accumulators early (independent stores overlap the tail below)
    {
        float* pl = &g_letter[0][0];
        for (int j = tid; j < VV * NSLOTS; j += 256) pl[j] = 0.f;
        float* ps = &g_scal[0][0];
        for (int j = tid; j < NSLOTS * 8; j += 256) ps[j] = 0.f;
    }

    // all-float tail: warp 0 computes frequency penalty in parallel
    if (warp == 0) {
        float ss[6];
#pragma unroll
        for (int q = 0; q < 6; q++)
            ss[q] = s_sc[0][q] + s_sc[1][q];

        float inv_me = 1.0f / ss[2];
        float d = 0.f;
        if (lane < VV) {
            d = s_sl[lane] * inv_me - c_freq[lane];
            d = fmaxf(d, 0.f);
        }
        float fp = wredf(d);

        if (lane == 0) {
            float rec_loss = ss[0] / ss[1];
            float kl_loss  = -0.5f * ss[4] * (1.0f / (float)(BB * LATENT));
            float cls_loss = -ss[5] * (1.0f / (float)BB);
            out[0] = rec_loss + 0.1f * kl_loss + 2.0f * cls_loss +
                     0.2f * ss[3] + 0.5f * fp;
        }
    }
}

extern "C" void kernel_launch(void* const* d_in, const int* in_sizes, int n_in,
                              void* d_out, int out_size) {
    (void)in_sizes; (void)n_in; (void)out_size;
    const float* x   = (const float*)d_in[0];
    const float* rec = (const float*)d_in[1];
    const float* zm  = (const float*)d_in[2];
    const float* zlv = (const float*)d_in[3];
    const float* cls = (const float*)d_in[4];

    vae_main<<<NGRID, TPB>>>(x, rec, zm, zlv, cls);

    // Finalize via PDL so its launch latency overlaps vae_main's execution.
    cudaLaunchConfig_t cfg = {};
    cfg.gridDim  = dim3(1, 1, 1);
    cfg.blockDim = dim3(256, 1, 1);
    cfg.dynamicSmemBytes = 0;
    cfg.stream = 0;
    cudaLaunchAttribute attrs[1];
    attrs[0].id = cudaLaunchAttributeProgrammaticStreamSerialization;
    attrs[0].val.programmaticStreamSerializationAllowed = 1;
    cfg.attrs = attrs;
    cfg.numAttrs = 1;
    float* outp = (float*)d_out;
    cudaLaunchKernelEx(&cfg, vae_finalize, outp);
}